// round 13
// baseline (speedup 1.0000x reference)
#include <cuda_runtime.h>

#define NG   64
#define NA   32
#define NN   2048
#define HID  128
#define FEAT 64

// scratch (static device globals — no runtime allocation)
__device__ __align__(16) float g_qkv[NN * 384];
__device__ __align__(16) float g_vals[NN * HID];
__device__ __align__(16) float g_emb[NG * HID];
// k-major (transposed, k-paired) dense weights
__device__ __align__(16) float2 g_W0T[64 * 106];   // [k2][c], K=128 -> 64 pairs
__device__ __align__(16) float2 g_W1T[53 * 85];    // K=106 -> 53 pairs
__device__ __align__(16) float2 g_W2T[43 * 64];    // K=85  -> 42 pairs + zero-padded pair

// packed f32x2 FMA: acc.{lo,hi} += a.{lo,hi} * b.{lo,hi}
__device__ __forceinline__ void fma2(unsigned long long& acc,
                                     unsigned long long a,
                                     unsigned long long b) {
    asm("fma.rn.f32x2 %0, %1, %2, %0;" : "+l"(acc) : "l"(a), "l"(b));
}
__device__ __forceinline__ float hsum2(unsigned long long a) {
    float lo = __uint_as_float((unsigned)(a & 0xffffffffull));
    float hi = __uint_as_float((unsigned)(a >> 32));
    return lo + hi;
}

// ---------------------------------------------------------------------------
// K_wT: one-time k-major repack of the dense weights.
// ---------------------------------------------------------------------------
#define N_W0T (64 * 106)
#define N_W1T (53 * 85)
#define N_W2T (43 * 64)
__global__ void k_wT(const float* __restrict__ W_d0,
                     const float* __restrict__ W_d1,
                     const float* __restrict__ W_d2) {
    int idx = blockIdx.x * 256 + threadIdx.x;
    if (idx < N_W0T) {
        int k2 = idx / 106, c = idx - k2 * 106;
        g_W0T[idx] = make_float2(W_d0[c * 128 + 2 * k2], W_d0[c * 128 + 2 * k2 + 1]);
    } else if (idx < N_W0T + N_W1T) {
        int j = idx - N_W0T;
        int k2 = j / 85, c = j - k2 * 85;
        g_W1T[j] = make_float2(W_d1[c * 106 + 2 * k2], W_d1[c * 106 + 2 * k2 + 1]);
    } else if (idx < N_W0T + N_W1T + N_W2T) {
        int j = idx - N_W0T - N_W1T;
        int k2 = j >> 6, c = j & 63;
        g_W2T[j] = (k2 < 42)
                 ? make_float2(W_d2[c * 85 + 2 * k2], W_d2[c * 85 + 2 * k2 + 1])
                 : make_float2(W_d2[c * 85 + 84], 0.f);
    }
}

// ---------------------------------------------------------------------------
// K_emb: g_emb[g, f] = sum_t next_type[g,t] * W_emb[f,t]
// ---------------------------------------------------------------------------
__global__ void k_emb(const float* __restrict__ next_type,
                      const float* __restrict__ W_emb) {
    __shared__ float nt[FEAT];
    __shared__ float weT[FEAT * 129];   // [t][f], stride 129

    const int g = blockIdx.x, tid = threadIdx.x;
    if (tid < FEAT) nt[tid] = next_type[g * FEAT + tid];

    const float4* w4 = (const float4*)W_emb;
#pragma unroll
    for (int it = 0; it < 16; it++) {
        int idx = tid + 128 * it;
        int f = idx >> 4, t4 = idx & 15;
        float4 w = w4[idx];
        weT[(t4 * 4 + 0) * 129 + f] = w.x;
        weT[(t4 * 4 + 1) * 129 + f] = w.y;
        weT[(t4 * 4 + 2) * 129 + f] = w.z;
        weT[(t4 * 4 + 3) * 129 + f] = w.w;
    }
    __syncthreads();

    float e = 0.f;
#pragma unroll
    for (int t = 0; t < FEAT; t++)
        e = fmaf(nt[t], weT[t * 129 + tid], e);
    g_emb[g * HID + tid] = e;
}

// ---------------------------------------------------------------------------
// K_qkv: g_qkv = (h ⊙ emb[graph]) @ W_qkv^T + b_qkv   (unchanged from R12)
// ---------------------------------------------------------------------------
__global__ void k_qkv(const float* __restrict__ h,
                      const float* __restrict__ W_qkv,
                      const float* __restrict__ b_qkv) {
    __shared__ __align__(16) float emb[HID];
    __shared__ __align__(16) float hs[32 * 132];
    __shared__ __align__(16) float Wsh[64 * 132];

    const int g = blockIdx.y, s = blockIdx.x, tid = threadIdx.x;
    if (tid < 32)
        ((float4*)emb)[tid] = ((const float4*)(g_emb + g * HID))[tid];
    __syncthreads();

    {
        const float4* h4 = (const float4*)(h + (size_t)g * NA * HID);
        for (int idx = tid; idx < 32 * 32; idx += 128) {
            int r = idx >> 5, c4 = idx & 31;
            *(float4*)&hs[r * 132 + c4 * 4] = h4[idx];
        }
    }
    const int gc0 = s * 64;
    {
        const float4* w4 = (const float4*)(W_qkv + (size_t)gc0 * HID);
        for (int idx = tid; idx < 64 * 32; idx += 128) {
            int c = idx >> 5, k4 = idx & 31;
            float4 w = w4[idx];
            float4 e = *(const float4*)&emb[k4 * 4];
            w.x *= e.x; w.y *= e.y; w.z *= e.z; w.w *= e.w;
            *(float4*)&Wsh[c * 132 + k4 * 4] = w;
        }
    }
    __syncthreads();

    const int rt = tid >> 4, ct = tid & 15;
    const int r0 = rt * 4;

    unsigned long long acc[4][4];
#pragma unroll
    for (int i = 0; i < 4; i++)
#pragma unroll
        for (int j = 0; j < 4; j++) acc[i][j] = 0ull;

#pragma unroll 2
    for (int k4 = 0; k4 < 32; k4++) {
        ulonglong2 a[4], w[4];
#pragma unroll
        for (int i = 0; i < 4; i++) a[i] = *(const ulonglong2*)&hs[(r0 + i) * 132 + k4 * 4];
#pragma unroll
        for (int j = 0; j < 4; j++) w[j] = *(const ulonglong2*)&Wsh[(ct + 16 * j) * 132 + k4 * 4];
#pragma unroll
        for (int i = 0; i < 4; i++)
#pragma unroll
            for (int j = 0; j < 4; j++) {
                fma2(acc[i][j], a[i].x, w[j].x);
                fma2(acc[i][j], a[i].y, w[j].y);
            }
    }

    const int row0 = g * NA + r0;
#pragma unroll
    for (int j = 0; j < 4; j++) {
        const int gc = gc0 + ct + 16 * j;
        float b = b_qkv[gc];
#pragma unroll
        for (int i = 0; i < 4; i++)
            g_qkv[(row0 + i) * 384 + gc] = hsum2(acc[i][j]) + b;
    }
}

// ---------------------------------------------------------------------------
// K_attn: per-graph 32x32 attention.  (unchanged from R12)
// ---------------------------------------------------------------------------
__global__ void k_attn(const float* __restrict__ h,
                       const float* __restrict__ pos,
                       const float* __restrict__ W_g,
                       const float* __restrict__ b_g,
                       const float* __restrict__ W_t,
                       const float* __restrict__ b_t) {
    extern __shared__ __align__(16) float sm[];
    float* xs  = sm;                 // 32*132
    float* qs  = xs + 32 * 132;      // 32*132
    float* ks  = qs + 32 * 132;      // 32*132
    float* vs  = ks + 32 * 132;      // 32*132
    float* att = vs + 32 * 132;      // 32*33
    float* px  = att + 32 * 33;      // 32
    float* py  = px + 32;            // 32
    float* pz  = py + 32;            // 32
    float* gs  = pz + 32;            // 32
    float* wt  = gs + 32;            // 32
    float* wg  = wt + 32;            // 128   (total 18240 floats)

    const int g = blockIdx.x, tid = threadIdx.x;
    if (tid < 32) wt[tid] = W_t[tid];
    else if (tid >= 64 && tid < 96) {
        int i = tid - 64;
        px[i] = pos[(g * NA + i) * 3 + 0];
        py[i] = pos[(g * NA + i) * 3 + 1];
        pz[i] = pos[(g * NA + i) * 3 + 2];
    } else if (tid >= 128) {
        wg[tid - 128] = W_g[tid - 128];
    }

    {
        const int f = tid & 127, ih = tid >> 7;
        const float e = g_emb[g * HID + f];
#pragma unroll
        for (int i = ih * 16; i < ih * 16 + 16; i++)
            xs[i * 132 + f] = h[(g * NA + i) * HID + f] * e;
    }

    const float4* q4 = (const float4*)g_qkv;
    for (int idx = tid; idx < NA * 96; idx += 256) {
        int row = idx / 96, c4 = idx - row * 96;
        float4 v = q4[(g * NA + row) * 96 + c4];
        int c = c4 * 4;
        float* dst = (c < 128) ? &qs[row * 132 + c]
                   : (c < 256) ? &ks[row * 132 + c - 128]
                               : &vs[row * 132 + c - 256];
        *(float4*)dst = v;
    }
    __syncthreads();

    {
        int i = tid >> 3, part = tid & 7;
        float a = 0.f;
#pragma unroll
        for (int t = 0; t < 16; t++) {
            int k = part * 16 + t;
            a = fmaf(xs[i * 132 + k], wg[k], a);
        }
        a += __shfl_xor_sync(0xffffffffu, a, 1);
        a += __shfl_xor_sync(0xffffffffu, a, 2);
        a += __shfl_xor_sync(0xffffffffu, a, 4);
        if (part == 0) gs[i] = 1.f / (1.f + __expf(-(a + b_g[0])));
    }

    const float RS = 0.17677669529663688f;   // 1/sqrt(32)
    const float bt0 = b_t[0];
#pragma unroll
    for (int m = 0; m < 4; m++) {
        int p = tid + 256 * m;
        int j = p >> 5, i = p & 31;
        float dx = px[i] - px[j], dy = py[i] - py[j], dz = pz[i] - pz[j];
        float sq = dx * dx + dy * dy + dz * dz;
        float d  = sqrtf(fmaxf(sq, 1e-12f));
        float t  = bt0;
#pragma unroll
        for (int kk = 0; kk < 32; kk++) {
            float u = d - kk * (10.f / 31.f);
            t = fmaf(wt[kk], __expf(-10.f * u * u), t);
        }
        unsigned long long acc = 0ull;
        const ulonglong2* qq = (const ulonglong2*)&qs[i * 132];
        const ulonglong2* kp = (const ulonglong2*)&ks[j * 132];
#pragma unroll 8
        for (int k4 = 0; k4 < 32; k4++) {
            ulonglong2 a = qq[k4], b = kp[k4];
            fma2(acc, a.x, b.x);
            fma2(acc, a.y, b.y);
        }
        att[i * 33 + j] = hsum2(acc) * RS + t;
    }
    __syncthreads();

    {
        int w = tid >> 5, lane = tid & 31;
#pragma unroll
        for (int rr = 0; rr < 4; rr++) {
            int r = w * 4 + rr;
            float v = att[r * 33 + lane];
            float mx = v;
#pragma unroll
            for (int o = 16; o > 0; o >>= 1) mx = fmaxf(mx, __shfl_xor_sync(0xffffffffu, mx, o));
            float e = __expf(v - mx);
            float ss = e;
#pragma unroll
            for (int o = 16; o > 0; o >>= 1) ss += __shfl_xor_sync(0xffffffffu, ss, o);
            att[r * 33 + lane] = e / ss;
        }
    }
    __syncthreads();

    {
        const int f = tid & 127, ih = tid >> 7;
        const int i0 = ih * 16;
        float acc[16];
#pragma unroll
        for (int i = 0; i < 16; i++) acc[i] = 0.f;
        for (int j = 0; j < NA; j++) {
            float vj = vs[j * 132 + f];
#pragma unroll
            for (int i = 0; i < 16; i++)
                acc[i] = fmaf(att[(i0 + i) * 33 + j], vj, acc[i]);
        }
#pragma unroll
        for (int i = 0; i < 16; i++)
            g_vals[(g * NA + i0 + i) * HID + f] =
                fmaf(acc[i], gs[i0 + i], xs[(i0 + i) * 132 + f]);
    }
}

// ---------------------------------------------------------------------------
// K_dense: 128 -> SiLU 106 -> SiLU 85 -> 64 -> log_softmax
// grid 512 (4 rows each), 128 threads.  NO weight smem: lane = out-channel,
// weights read coalesced from k-major g_W*T (L1-resident, 116 KB total).
// ---------------------------------------------------------------------------
__global__ void k_dense(const float* __restrict__ b_d0,
                        const float* __restrict__ b_d1,
                        const float* __restrict__ b_d2,
                        float* __restrict__ out) {
    __shared__ __align__(16) float xs[4 * 132];   // row stride 132 (528B, ÷16)
    __shared__ __align__(8)  float y0[4 * 108];   // stride 432B ÷8
    __shared__ __align__(8)  float y1[4 * 88];    // stride 352B ÷8
    __shared__ __align__(8)  float y2[4 * 66];

    const int tid  = threadIdx.x;
    const int row0 = blockIdx.x * 4;

    // stage x rows (4 x 128 -> 128 float4s, one per thread)
    {
        const float4* v4 = (const float4*)(g_vals + (size_t)row0 * HID);
        int r = tid >> 5, c4 = tid & 31;
        *(float4*)&xs[r * 132 + c4 * 4] = v4[tid];
    }
    // zero the K=85 pad column of y1 (read by the padded 43rd weight pair)
    if (tid < 4) y1[tid * 88 + 85] = 0.f;
    __syncthreads();

    // layer 0: K=128 (64 pairs), 106 outputs, lane = c, 4 rows
    if (tid < 106) {
        const int c = tid;
        unsigned long long acc[4] = {0ull, 0ull, 0ull, 0ull};
        const unsigned long long* wp = (const unsigned long long*)g_W0T;
#pragma unroll 8
        for (int k2 = 0; k2 < 64; k2++) {
            unsigned long long w = wp[k2 * 106 + c];
#pragma unroll
            for (int r = 0; r < 4; r++) {
                unsigned long long x = *(const unsigned long long*)&xs[r * 132 + k2 * 2];
                fma2(acc[r], x, w);
            }
        }
        float b = __ldg(&b_d0[c]);
#pragma unroll
        for (int r = 0; r < 4; r++) {
            float z = hsum2(acc[r]) + b;
            y0[r * 108 + c] = z / (1.f + __expf(-z));
        }
    }
    __syncthreads();

    // layer 1: K=106 (53 pairs), 85 outputs
    if (tid < 85) {
        const int c = tid;
        unsigned long long acc[4] = {0ull, 0ull, 0ull, 0ull};
        const unsigned long long* wp = (const unsigned long long*)g_W1T;
#pragma unroll 8
        for (int k2 = 0; k2 < 53; k2++) {
            unsigned long long w = wp[k2 * 85 + c];
#pragma unroll
            for (int r = 0; r < 4; r++) {
                unsigned long long x = *(const unsigned long long*)&y0[r * 108 + k2 * 2];
                fma2(acc[r], x, w);
            }
        }
        float b = __ldg(&b_d1[c]);
#pragma unroll
        for (int r = 0; r < 4; r++) {
            float z = hsum2(acc[r]) + b;
            y1[r * 88 + c] = z / (1.f + __expf(-z));
        }
    }
    __syncthreads();

    // layer 2: K=85 (43 pairs, last zero-padded), 64 outputs, 2 row-groups
    {
        const int c = tid & 63, rg = tid >> 6;     // rg in {0,1}, 2 rows each
        unsigned long long acc[2] = {0ull, 0ull};
        const unsigned long long* wp = (const unsigned long long*)g_W2T;
#pragma unroll 8
        for (int k2 = 0; k2 < 43; k2++) {
            unsigned long long w = wp[(k2 << 6) + c];
#pragma unroll
            for (int r = 0; r < 2; r++) {
                unsigned long long x = *(const unsigned long long*)&y1[(rg * 2 + r) * 88 + k2 * 2];
                fma2(acc[r], x, w);
            }
        }
        float b = __ldg(&b_d2[c]);
#pragma unroll
        for (int r = 0; r < 2; r++)
            y2[(rg * 2 + r) * 66 + c] = hsum2(acc[r]) + b;
    }
    __syncthreads();

    // log_softmax over 64: 4 warps x 1 row
    {
        int w = tid >> 5, lane = tid & 31;
        float e0 = y2[w * 66 + lane], e1 = y2[w * 66 + lane + 32];
        float mx = fmaxf(e0, e1);
#pragma unroll
        for (int o = 16; o > 0; o >>= 1) mx = fmaxf(mx, __shfl_xor_sync(0xffffffffu, mx, o));
        float s = __expf(e0 - mx) + __expf(e1 - mx);
#pragma unroll
        for (int o = 16; o > 0; o >>= 1) s += __shfl_xor_sync(0xffffffffu, s, o);
        float l = mx + __logf(s);
        out[(row0 + w) * 64 + lane]      = e0 - l;
        out[(row0 + w) * 64 + lane + 32] = e1 - l;
    }
}

// ---------------------------------------------------------------------------
extern "C" void kernel_launch(void* const* d_in, const int* in_sizes, int n_in,
                              void* d_out, int out_size) {
    const float* h         = (const float*)d_in[0];
    const float* pos       = (const float*)d_in[1];
    const float* next_type = (const float*)d_in[2];
    // d_in[3] = batch (int32) — structure fixed (arange//32), unused
    const float* W_emb = (const float*)d_in[4];
    const float* W_qkv = (const float*)d_in[5];
    const float* b_qkv = (const float*)d_in[6];
    // d_in[7] W_b, d_in[8] b_b — per-row bias cancels inside softmax, unused
    const float* W_g  = (const float*)d_in[9];
    const float* b_g  = (const float*)d_in[10];
    const float* W_t  = (const float*)d_in[11];
    const float* b_t  = (const float*)d_in[12];
    const float* W_d0 = (const float*)d_in[13];
    const float* b_d0 = (const float*)d_in[14];
    const float* W_d1 = (const float*)d_in[15];
    const float* b_d1 = (const float*)d_in[16];
    const float* W_d2 = (const float*)d_in[17];
    const float* b_d2 = (const float*)d_in[18];
    float* out = (float*)d_out;

    const int smem_attn = 18240 * 4;   // 72960 B
    cudaFuncSetAttribute(k_attn, cudaFuncAttributeMaxDynamicSharedMemorySize, smem_attn);

    k_wT<<<56, 256>>>(W_d0, W_d1, W_d2);
    k_emb<<<64, 128>>>(next_type, W_emb);
    k_qkv<<<dim3(6, 64), 128>>>(h, W_qkv, b_qkv);
    k_attn<<<64, 256, smem_attn>>>(h, pos, W_g, b_g, W_t, b_t);
    k_dense<<<512, 128>>>(b_d0, b_d1, b_d2, out);
}

// round 14
// speedup vs baseline: 1.2092x; 1.2092x over previous
#include <cuda_runtime.h>

#define NG   64
#define NA   32
#define NN   2048
#define HID  128
#define FEAT 64

// scratch (static device globals — no runtime allocation)
__device__ __align__(16) float g_qkv[NN * 384];
__device__ __align__(16) float g_vals[NN * HID];
__device__ __align__(16) float g_emb[NG * HID];
// k-major (transposed, k-paired) dense weights
__device__ __align__(16) float2 g_W0T[64 * 106];   // [k2][c], K=128 -> 64 pairs
__device__ __align__(16) float2 g_W1T[53 * 85];    // K=106 -> 53 pairs
__device__ __align__(16) float2 g_W2T[43 * 64];    // K=85  -> 42 pairs + zero-padded pair

// packed f32x2 FMA: acc.{lo,hi} += a.{lo,hi} * b.{lo,hi}
__device__ __forceinline__ void fma2(unsigned long long& acc,
                                     unsigned long long a,
                                     unsigned long long b) {
    asm("fma.rn.f32x2 %0, %1, %2, %0;" : "+l"(acc) : "l"(a), "l"(b));
}
__device__ __forceinline__ float hsum2(unsigned long long a) {
    float lo = __uint_as_float((unsigned)(a & 0xffffffffull));
    float hi = __uint_as_float((unsigned)(a >> 32));
    return lo + hi;
}

// ---------------------------------------------------------------------------
// K_prep: blocks 0-55 repack dense weights k-major; blocks 56-119 compute emb.
// ---------------------------------------------------------------------------
#define N_W0T (64 * 106)
#define N_W1T (53 * 85)
#define N_W2T (43 * 64)
__global__ void k_prep(const float* __restrict__ next_type,
                       const float* __restrict__ W_emb,
                       const float* __restrict__ W_d0,
                       const float* __restrict__ W_d1,
                       const float* __restrict__ W_d2) {
    const int tid = threadIdx.x;
    if (blockIdx.x < 56) {
        int idx = blockIdx.x * 256 + tid;
        if (idx < N_W0T) {
            int k2 = idx / 106, c = idx - k2 * 106;
            g_W0T[idx] = make_float2(W_d0[c * 128 + 2 * k2], W_d0[c * 128 + 2 * k2 + 1]);
        } else if (idx < N_W0T + N_W1T) {
            int j = idx - N_W0T;
            int k2 = j / 85, c = j - k2 * 85;
            g_W1T[j] = make_float2(W_d1[c * 106 + 2 * k2], W_d1[c * 106 + 2 * k2 + 1]);
        } else if (idx < N_W0T + N_W1T + N_W2T) {
            int j = idx - N_W0T - N_W1T;
            int k2 = j >> 6, c = j & 63;
            g_W2T[j] = (k2 < 42)
                     ? make_float2(W_d2[c * 85 + 2 * k2], W_d2[c * 85 + 2 * k2 + 1])
                     : make_float2(W_d2[c * 85 + 84], 0.f);
        }
    } else {
        __shared__ float nt[FEAT];
        __shared__ float weT[FEAT * 129];   // [t][f], stride 129
        const int g = blockIdx.x - 56;
        if (tid < FEAT) nt[tid] = next_type[g * FEAT + tid];
        const float4* w4 = (const float4*)W_emb;
#pragma unroll
        for (int it = 0; it < 8; it++) {
            int idx = tid + 256 * it;            // over 2048 float4s
            int f = idx >> 4, t4 = idx & 15;
            float4 w = w4[idx];
            weT[(t4 * 4 + 0) * 129 + f] = w.x;
            weT[(t4 * 4 + 1) * 129 + f] = w.y;
            weT[(t4 * 4 + 2) * 129 + f] = w.z;
            weT[(t4 * 4 + 3) * 129 + f] = w.w;
        }
        __syncthreads();
        if (tid < HID) {
            float e = 0.f;
#pragma unroll
            for (int t = 0; t < FEAT; t++)
                e = fmaf(nt[t], weT[t * 129 + tid], e);
            g_emb[g * HID + tid] = e;
        }
    }
}

// ---------------------------------------------------------------------------
// K_qkv: g_qkv = (h ⊙ emb[graph]) @ W_qkv^T + b_qkv   (validated, unchanged)
// ---------------------------------------------------------------------------
__global__ void k_qkv(const float* __restrict__ h,
                      const float* __restrict__ W_qkv,
                      const float* __restrict__ b_qkv) {
    __shared__ __align__(16) float emb[HID];
    __shared__ __align__(16) float hs[32 * 132];
    __shared__ __align__(16) float Wsh[64 * 132];

    const int g = blockIdx.y, s = blockIdx.x, tid = threadIdx.x;
    if (tid < 32)
        ((float4*)emb)[tid] = ((const float4*)(g_emb + g * HID))[tid];
    __syncthreads();

    {
        const float4* h4 = (const float4*)(h + (size_t)g * NA * HID);
        for (int idx = tid; idx < 32 * 32; idx += 128) {
            int r = idx >> 5, c4 = idx & 31;
            *(float4*)&hs[r * 132 + c4 * 4] = h4[idx];
        }
    }
    const int gc0 = s * 64;
    {
        const float4* w4 = (const float4*)(W_qkv + (size_t)gc0 * HID);
        for (int idx = tid; idx < 64 * 32; idx += 128) {
            int c = idx >> 5, k4 = idx & 31;
            float4 w = w4[idx];
            float4 e = *(const float4*)&emb[k4 * 4];
            w.x *= e.x; w.y *= e.y; w.z *= e.z; w.w *= e.w;
            *(float4*)&Wsh[c * 132 + k4 * 4] = w;
        }
    }
    __syncthreads();

    const int rt = tid >> 4, ct = tid & 15;
    const int r0 = rt * 4;

    unsigned long long acc[4][4];
#pragma unroll
    for (int i = 0; i < 4; i++)
#pragma unroll
        for (int j = 0; j < 4; j++) acc[i][j] = 0ull;

#pragma unroll 2
    for (int k4 = 0; k4 < 32; k4++) {
        ulonglong2 a[4], w[4];
#pragma unroll
        for (int i = 0; i < 4; i++) a[i] = *(const ulonglong2*)&hs[(r0 + i) * 132 + k4 * 4];
#pragma unroll
        for (int j = 0; j < 4; j++) w[j] = *(const ulonglong2*)&Wsh[(ct + 16 * j) * 132 + k4 * 4];
#pragma unroll
        for (int i = 0; i < 4; i++)
#pragma unroll
            for (int j = 0; j < 4; j++) {
                fma2(acc[i][j], a[i].x, w[j].x);
                fma2(acc[i][j], a[i].y, w[j].y);
            }
    }

    const int row0 = g * NA + r0;
#pragma unroll
    for (int j = 0; j < 4; j++) {
        const int gc = gc0 + ct + 16 * j;
        float b = b_qkv[gc];
#pragma unroll
        for (int i = 0; i < 4; i++)
            g_qkv[(row0 + i) * 384 + gc] = hsum2(acc[i][j]) + b;
    }
}

// ---------------------------------------------------------------------------
// K_attn: grid (4 q-slices, 64 graphs), 256 threads, static smem (~44 KB).
// Each block: 8 query rows vs all 32 keys.  One logit pair per thread.
// ---------------------------------------------------------------------------
__global__ void k_attn(const float* __restrict__ h,
                       const float* __restrict__ pos,
                       const float* __restrict__ W_g,
                       const float* __restrict__ b_g,
                       const float* __restrict__ W_t,
                       const float* __restrict__ b_t) {
    __shared__ __align__(16) float ks[32 * 132];
    __shared__ __align__(16) float vs[32 * 132];
    __shared__ __align__(16) float xs[8 * 132];
    __shared__ __align__(16) float qs[8 * 132];
    __shared__ float att[8 * 33];
    __shared__ float px[32], py[32], pz[32];
    __shared__ float gs[8];
    __shared__ float wt[32];
    __shared__ float wg[128];

    const int g = blockIdx.y, tid = threadIdx.x;
    const int i0 = blockIdx.x * 8;             // first query row of this block

    if (tid < 32) wt[tid] = W_t[tid];
    else if (tid >= 64 && tid < 96) {
        int i = tid - 64;
        px[i] = pos[(g * NA + i) * 3 + 0];
        py[i] = pos[(g * NA + i) * 3 + 1];
        pz[i] = pos[(g * NA + i) * 3 + 2];
    } else if (tid >= 128) {
        wg[tid - 128] = W_g[tid - 128];
    }

    // xs = h * emb for own 8 rows: thread = (feature, row-half of 4)
    {
        const int f = tid & 127, rh = tid >> 7;
        const float e = g_emb[g * HID + f];
#pragma unroll
        for (int r = rh * 4; r < rh * 4 + 4; r++)
            xs[r * 132 + f] = h[(g * NA + i0 + r) * HID + f] * e;
    }

    // q for own 8 rows (256 float4s, 1/thread); k,v for all 32 rows (4/thread)
    const float4* q4 = (const float4*)g_qkv;
    {
        int r = tid >> 5, c4 = tid & 31;
        *(float4*)&qs[r * 132 + c4 * 4] = q4[(size_t)(g * NA + i0 + r) * 96 + c4];
    }
#pragma unroll
    for (int m = 0; m < 4; m++) {
        int idx = tid + 256 * m;
        int r = idx >> 5, c4 = idx & 31;
        size_t base = (size_t)(g * NA + r) * 96;
        *(float4*)&ks[r * 132 + c4 * 4] = q4[base + 32 + c4];
        *(float4*)&vs[r * 132 + c4 * 4] = q4[base + 64 + c4];
    }
    __syncthreads();

    // gate for own 8 rows: 1 warp per row, 4 feats/lane, shfl reduce
    {
        int i = tid >> 5, part = tid & 31;
        float4 x = *(const float4*)&xs[i * 132 + part * 4];
        float4 w = *(const float4*)&wg[part * 4];
        float a = x.x * w.x + x.y * w.y + x.z * w.z + x.w * w.w;
#pragma unroll
        for (int o = 16; o > 0; o >>= 1) a += __shfl_xor_sync(0xffffffffu, a, o);
        if (part == 0) gs[i] = 1.f / (1.f + __expf(-(a + b_g[0])));
    }

    // logits: 1 pair per thread; i = warp (q broadcast), j = lane (ks spread)
    const float RS = 0.17677669529663688f;   // 1/sqrt(32)
    {
        const int i = tid >> 5, j = tid & 31;
        const int ig = i0 + i;
        float dx = px[ig] - px[j], dy = py[ig] - py[j], dz = pz[ig] - pz[j];
        float sq = dx * dx + dy * dy + dz * dz;
        float d  = sqrtf(fmaxf(sq, 1e-12f));
        float t  = b_t[0];
#pragma unroll
        for (int kk = 0; kk < 32; kk++) {
            float u = d - kk * (10.f / 31.f);
            t = fmaf(wt[kk], __expf(-10.f * u * u), t);
        }
        unsigned long long acc = 0ull;
        const ulonglong2* qq = (const ulonglong2*)&qs[i * 132];
        const ulonglong2* kp = (const ulonglong2*)&ks[j * 132];
#pragma unroll 8
        for (int k4 = 0; k4 < 32; k4++) {
            ulonglong2 a = qq[k4], b = kp[k4];
            fma2(acc, a.x, b.x);
            fma2(acc, a.y, b.y);
        }
        att[i * 33 + j] = hsum2(acc) * RS + t;
    }
    __syncthreads();

    // softmax: 1 warp per row
    {
        int r = tid >> 5, lane = tid & 31;
        float v = att[r * 33 + lane];
        float mx = v;
#pragma unroll
        for (int o = 16; o > 0; o >>= 1) mx = fmaxf(mx, __shfl_xor_sync(0xffffffffu, mx, o));
        float e = __expf(v - mx);
        float ss = e;
#pragma unroll
        for (int o = 16; o > 0; o >>= 1) ss += __shfl_xor_sync(0xffffffffu, ss, o);
        att[r * 33 + lane] = e / ss;
    }
    __syncthreads();

    // out: thread = (feature f, 4-row half); vs[j][f] conflict-free, att broadcast
    {
        const int f = tid & 127, rh = tid >> 7;
        float acc[4] = {0.f, 0.f, 0.f, 0.f};
        for (int j = 0; j < NA; j++) {
            float vj = vs[j * 132 + f];
#pragma unroll
            for (int r = 0; r < 4; r++)
                acc[r] = fmaf(att[(rh * 4 + r) * 33 + j], vj, acc[r]);
        }
#pragma unroll
        for (int r = 0; r < 4; r++) {
            int i = rh * 4 + r;
            g_vals[(g * NA + i0 + i) * HID + f] =
                fmaf(acc[r], gs[i], xs[i * 132 + f]);
        }
    }
}

// ---------------------------------------------------------------------------
// K_dense: 128 -> SiLU 106 -> SiLU 85 -> 64 -> log_softmax
// grid 512 (4 rows each), 128 threads.  (validated, unchanged)
// ---------------------------------------------------------------------------
__global__ void k_dense(const float* __restrict__ b_d0,
                        const float* __restrict__ b_d1,
                        const float* __restrict__ b_d2,
                        float* __restrict__ out) {
    __shared__ __align__(16) float xs[4 * 132];
    __shared__ __align__(8)  float y0[4 * 108];
    __shared__ __align__(8)  float y1[4 * 88];
    __shared__ __align__(8)  float y2[4 * 66];

    const int tid  = threadIdx.x;
    const int row0 = blockIdx.x * 4;

    {
        const float4* v4 = (const float4*)(g_vals + (size_t)row0 * HID);
        int r = tid >> 5, c4 = tid & 31;
        *(float4*)&xs[r * 132 + c4 * 4] = v4[tid];
    }
    if (tid < 4) y1[tid * 88 + 85] = 0.f;     // zero pad column for 43rd pair
    __syncthreads();

    if (tid < 106) {
        const int c = tid;
        unsigned long long acc[4] = {0ull, 0ull, 0ull, 0ull};
        const unsigned long long* wp = (const unsigned long long*)g_W0T;
#pragma unroll 8
        for (int k2 = 0; k2 < 64; k2++) {
            unsigned long long w = wp[k2 * 106 + c];
#pragma unroll
            for (int r = 0; r < 4; r++) {
                unsigned long long x = *(const unsigned long long*)&xs[r * 132 + k2 * 2];
                fma2(acc[r], x, w);
            }
        }
        float b = __ldg(&b_d0[c]);
#pragma unroll
        for (int r = 0; r < 4; r++) {
            float z = hsum2(acc[r]) + b;
            y0[r * 108 + c] = z / (1.f + __expf(-z));
        }
    }
    __syncthreads();

    if (tid < 85) {
        const int c = tid;
        unsigned long long acc[4] = {0ull, 0ull, 0ull, 0ull};
        const unsigned long long* wp = (const unsigned long long*)g_W1T;
#pragma unroll 8
        for (int k2 = 0; k2 < 53; k2++) {
            unsigned long long w = wp[k2 * 85 + c];
#pragma unroll
            for (int r = 0; r < 4; r++) {
                unsigned long long x = *(const unsigned long long*)&y0[r * 108 + k2 * 2];
                fma2(acc[r], x, w);
            }
        }
        float b = __ldg(&b_d1[c]);
#pragma unroll
        for (int r = 0; r < 4; r++) {
            float z = hsum2(acc[r]) + b;
            y1[r * 88 + c] = z / (1.f + __expf(-z));
        }
    }
    __syncthreads();

    {
        const int c = tid & 63, rg = tid >> 6;
        unsigned long long acc[2] = {0ull, 0ull};
        const unsigned long long* wp = (const unsigned long long*)g_W2T;
#pragma unroll 8
        for (int k2 = 0; k2 < 43; k2++) {
            unsigned long long w = wp[(k2 << 6) + c];
#pragma unroll
            for (int r = 0; r < 2; r++) {
                unsigned long long x = *(const unsigned long long*)&y1[(rg * 2 + r) * 88 + k2 * 2];
                fma2(acc[r], x, w);
            }
        }
        float b = __ldg(&b_d2[c]);
#pragma unroll
        for (int r = 0; r < 2; r++)
            y2[(rg * 2 + r) * 66 + c] = hsum2(acc[r]) + b;
    }
    __syncthreads();

    {
        int w = tid >> 5, lane = tid & 31;
        float e0 = y2[w * 66 + lane], e1 = y2[w * 66 + lane + 32];
        float mx = fmaxf(e0, e1);
#pragma unroll
        for (int o = 16; o > 0; o >>= 1) mx = fmaxf(mx, __shfl_xor_sync(0xffffffffu, mx, o));
        float s = __expf(e0 - mx) + __expf(e1 - mx);
#pragma unroll
        for (int o = 16; o > 0; o >>= 1) s += __shfl_xor_sync(0xffffffffu, s, o);
        float l = mx + __logf(s);
        out[(row0 + w) * 64 + lane]      = e0 - l;
        out[(row0 + w) * 64 + lane + 32] = e1 - l;
    }
}

// ---------------------------------------------------------------------------
extern "C" void kernel_launch(void* const* d_in, const int* in_sizes, int n_in,
                              void* d_out, int out_size) {
    const float* h         = (const float*)d_in[0];
    const float* pos       = (const float*)d_in[1];
    const float* next_type = (const float*)d_in[2];
    // d_in[3] = batch (int32) — structure fixed (arange//32), unused
    const float* W_emb = (const float*)d_in[4];
    const float* W_qkv = (const float*)d_in[5];
    const float* b_qkv = (const float*)d_in[6];
    // d_in[7] W_b, d_in[8] b_b — per-row bias cancels inside softmax, unused
    const float* W_g  = (const float*)d_in[9];
    const float* b_g  = (const float*)d_in[10];
    const float* W_t  = (const float*)d_in[11];
    const float* b_t  = (const float*)d_in[12];
    const float* W_d0 = (const float*)d_in[13];
    const float* b_d0 = (const float*)d_in[14];
    const float* W_d1 = (const float*)d_in[15];
    const float* b_d1 = (const float*)d_in[16];
    const float* W_d2 = (const float*)d_in[17];
    const float* b_d2 = (const float*)d_in[18];
    float* out = (float*)d_out;

    k_prep<<<120, 256>>>(next_type, W_emb, W_d0, W_d1, W_d2);
    k_qkv<<<dim3(6, 64), 128>>>(h, W_qkv, b_qkv);
    k_attn<<<dim3(4, 64), 256>>>(h, pos, W_g, b_g, W_t, b_t);
    k_dense<<<512, 128>>>(b_d0, b_d1, b_d2, out);
}